// round 8
// baseline (speedup 1.0000x reference)
#include <cuda_runtime.h>
#include <math.h>

#define B_MAX    4000000
#define BLOCKS   592        // 148 SMs * 4, all co-resident (required for barrier)
#define NTHREADS 256
#define PTS_MAX  6784       // >= ceil(B_MAX / BLOCKS) = 6758

__device__ float             g_blockmax[BLOCKS];
__device__ float             g_partials[BLOCKS];
__device__ unsigned int      g_bar_count = 0;
__device__ volatile unsigned g_bar_flag  = 0;
__device__ unsigned int      g_ticket    = 0;

// ---------------------------------------------------------------------------
// Packed f32x2 primitives (sm_103a FFMA2/FADD2/FMUL2 — PTX-only, ptxas never
// auto-fuses). Per-lane IEEE rn semantics identical to scalar ops.
typedef unsigned long long u64;

__device__ __forceinline__ u64 f2pack(float lo, float hi) {
    u64 r; asm("mov.b64 %0, {%1, %2};" : "=l"(r) : "f"(lo), "f"(hi)); return r;
}
__device__ __forceinline__ void f2unpack(u64 v, float& lo, float& hi) {
    asm("mov.b64 {%0, %1}, %2;" : "=f"(lo), "=f"(hi) : "l"(v));
}
__device__ __forceinline__ u64 f2add(u64 a, u64 b) {
    u64 d; asm("add.rn.f32x2 %0, %1, %2;" : "=l"(d) : "l"(a), "l"(b)); return d;
}
__device__ __forceinline__ u64 f2mul(u64 a, u64 b) {
    u64 d; asm("mul.rn.f32x2 %0, %1, %2;" : "=l"(d) : "l"(a), "l"(b)); return d;
}
__device__ __forceinline__ u64 f2fma(u64 a, u64 b, u64 c) {
    u64 d; asm("fma.rn.f32x2 %0, %1, %2, %3;" : "=l"(d) : "l"(a), "l"(b), "l"(c)); return d;
}
__device__ __forceinline__ u64 f2neg(u64 a) { return a ^ 0x8000000080000000ULL; }
__device__ __forceinline__ u64 f2sub(u64 a, u64 b) { return f2add(a, f2neg(b)); }
__device__ __forceinline__ u64 f2bc(float c) { return f2pack(c, c); }

// ---------------------------------------------------------------------------
// Double-float sincos for TWO angles simultaneously (packed f32x2 lanes).
// Per-lane op sequence is bitwise identical to the scalar DF sincos: abs error
// ~2^-31, matching correctly-rounded f32 except on a tiny near-tie sliver.
__device__ __forceinline__ void df_sincos2(float xa, float xb,
                                           float& sa, float& ca,
                                           float& sb, float& cb) {
    const float TWO_OVER_PI = 0.63661977236758134f;
    const float C1 = 1.57079637050628662109375f;   // float(pi/2)
    const float C2 = -4.37113900018624283e-8f;     // pi/2 - C1 (rounded)

    float qfa = rintf(xa * TWO_OVER_PI);           // q in {-2..2}
    float qfb = rintf(xb * TWO_OVER_PI);
    int na = (int)qfa, nb = (int)qfb;

    u64 x  = f2pack(xa, xb);
    u64 qf = f2pack(qfa, qfb);

    u64 a   = f2fma(qf, f2bc(-C1), x);             // exact
    u64 b   = f2mul(qf, f2bc(-C2));
    u64 rhi = f2add(a, b);                         // TwoSum
    u64 bp  = f2sub(rhi, a);
    u64 rlo = f2add(f2sub(a, f2sub(rhi, bp)), f2sub(b, bp));

    u64 r2h = f2mul(rhi, rhi);
    u64 r2l = f2fma(rhi, rhi, f2neg(r2h));
    r2l = f2fma(f2add(rhi, rhi), rlo, r2l);

    // ---- sin(r) = r + r^3 * V(r^2), V through r^11 ----
    const float c11 = -2.50521083854417202e-8f;
    const float c9  =  2.75573192239858907e-6f;
    const float c7  = -1.98412698412698413e-4f;
    const float c5  =  8.33333333333333333e-3f;
    const float c3h = -0.16666667163372039794921875f;
    const float c3l =  4.96705424632835143e-9f;

    u64 Q  = f2fma(r2h, f2bc(c11), f2bc(c9));
    u64 T  = f2fma(r2h, Q, f2bc(c7));
    u64 U  = f2fma(r2h, T, f2bc(c5));
    u64 ph = f2mul(r2h, U);
    u64 pl = f2fma(r2h, U, f2neg(ph));
    u64 vh = f2add(f2bc(c3h), ph);
    u64 vl = f2add(f2add(f2add(f2sub(f2bc(c3h), vh), ph), pl), f2bc(c3l));
    u64 wh = f2mul(r2h, rhi);                      // r^3
    u64 wl = f2fma(r2h, rhi, f2neg(wh));
    wl = f2fma(r2h, rlo, wl);
    u64 th = f2mul(wh, vh);
    u64 tl = f2fma(wh, vh, f2neg(th));
    tl = f2fma(wh, vl, tl);
    tl = f2fma(wl, vh, tl);
    u64 sh = f2add(rhi, th);
    u64 sl = f2add(f2add(f2add(f2sub(rhi, sh), th), tl), rlo);
    u64 sinr = f2add(sh, sl);

    // ---- cos(r) = (1 - r^2/2) + r^4 * E(r^2) ----
    const float e16 =  2.08767569878680990e-9f;
    const float e10 = -2.75573192239858907e-7f;
    const float e8  =  2.48015873015873016e-5f;
    const float e6  = -1.38888888888888889e-3f;
    const float c4h =  0.041666667908430099487304688f;
    const float c4l = -1.24176630587859679e-9f;

    u64 F = f2fma(r2h, f2bc(e16), f2bc(e10));
    F = f2fma(r2h, F, f2bc(e8));
    F = f2fma(r2h, F, f2bc(e6));
    u64 eh0 = f2mul(r2h, F);
    u64 el0 = f2fma(r2h, F, f2neg(eh0));
    u64 Eh  = f2add(f2bc(c4h), eh0);
    u64 El  = f2add(f2add(f2add(f2sub(f2bc(c4h), Eh), eh0), el0), f2bc(c4l));
    u64 r4h = f2mul(r2h, r2h);
    u64 kh  = f2mul(r4h, Eh);
    u64 kl  = f2fma(r4h, Eh, f2neg(kh));
    kl = f2fma(r4h, El, kl);
    u64 hh = f2mul(f2bc(0.5f), r2h);
    u64 Ah = f2sub(f2bc(1.0f), hh);
    u64 Al = f2sub(f2sub(f2bc(1.0f), Ah), hh);
    Al = f2fma(f2bc(-0.5f), r2l, Al);
    u64 ch = f2add(Ah, kh);
    u64 cl = f2add(f2add(f2add(f2sub(Ah, ch), kh), kl), Al);
    u64 cosr = f2add(ch, cl);

    // ---- unpack + per-angle quadrant fixup ----
    float sra, srb, cra, crb;
    f2unpack(sinr, sra, srb);
    f2unpack(cosr, cra, crb);

    int ma = na & 3;
    float s0 = (ma & 1) ? cra : sra;
    float c0 = (ma & 1) ? sra : cra;
    if (ma & 2)       s0 = -s0;
    if ((ma + 1) & 2) c0 = -c0;
    sa = s0; ca = c0;

    int mb = nb & 3;
    float s1 = (mb & 1) ? crb : srb;
    float c1 = (mb & 1) ? srb : crb;
    if (mb & 2)       s1 = -s1;
    if ((mb + 1) & 2) c1 = -c1;
    sb = s1; cb = c1;
}

// ---------------------------------------------------------------------------
__device__ __forceinline__ float enu_dist(const float* __restrict__ inp,
                                          const float* __restrict__ tgt, int i) {
    const float DEG2RAD = 0.017453292519943295f;
    const float E2      = 0.00669437999014f;
    const float A       = 6378137.0f;
    const float C1mE2   = 0.99330562000986f;

    float lat = tgt[3 * i + 0];
    float lon = tgt[3 * i + 1];
    float h   = tgt[3 * i + 2];

    float latr = __fmul_rn(lat, DEG2RAD);
    float lonr = __fmul_rn(lon, DEG2RAD);

    float sl, cl, so, co;
    df_sincos2(latr, lonr, sl, cl, so, co);

    // exact replication of reference f32 sequence (no FMA contraction)
    float t  = __fsub_rn(1.0f, __fmul_rn(__fmul_rn(E2, sl), sl));
    float N  = __fdiv_rn(A, __fsqrt_rn(t));
    float Nh = __fadd_rn(N, h);
    float Nhcl = __fmul_rn(Nh, cl);
    float rx = __fmul_rn(Nhcl, co);
    float ry = __fmul_rn(Nhcl, so);
    float rz = __fmul_rn(__fadd_rn(__fmul_rn(N, C1mE2), h), sl);

    float dx = __fsub_rn(inp[3 * i + 0], rx);
    float dy = __fsub_rn(inp[3 * i + 1], ry);
    float dz = __fsub_rn(inp[3 * i + 2], rz);

    float e = -so * dx + co * dy;
    float n = -sl * co * dx - sl * so * dy + cl * dz;
    float u =  cl * co * dx + cl * so * dy + sl * dz;

    return sqrtf(e * e + n * n + u * u);
}

// ---------------------------------------------------------------------------
// Fused persistent kernel: dist -> smem, grid barrier for global max, focal
// sum, deterministic last-block finish.
__global__ void __launch_bounds__(NTHREADS, 4)
k_fused(const float* __restrict__ inp, const float* __restrict__ tgt,
        float* __restrict__ out, int B) {
    __shared__ float s_dist[PTS_MAX];
    __shared__ float s_red[NTHREADS / 32];

    int chunk = (B + BLOCKS - 1) / BLOCKS;          // <= PTS_MAX
    int start = blockIdx.x * chunk;
    int cnt   = min(chunk, B - start);
    if (cnt < 0) cnt = 0;

    int lane = threadIdx.x & 31, wid = threadIdx.x >> 5;

    // ---------------- Phase 1: distances -> smem, block max ----------------
    float local_max = 0.0f;
    int k = threadIdx.x;
    for (; k + NTHREADS < cnt; k += 2 * NTHREADS) {   // 2-way unroll for ILP
        float d0 = enu_dist(inp, tgt, start + k);
        float d1 = enu_dist(inp, tgt, start + k + NTHREADS);
        s_dist[k] = d0;
        s_dist[k + NTHREADS] = d1;
        local_max = fmaxf(local_max, fmaxf(d0, d1));
    }
    if (k < cnt) {
        float d0 = enu_dist(inp, tgt, start + k);
        s_dist[k] = d0;
        local_max = fmaxf(local_max, d0);
    }

    #pragma unroll
    for (int o = 16; o > 0; o >>= 1)
        local_max = fmaxf(local_max, __shfl_xor_sync(0xFFFFFFFFu, local_max, o));
    if (lane == 0) s_red[wid] = local_max;
    __syncthreads();
    if (wid == 0) {
        float v = (lane < NTHREADS / 32) ? s_red[lane] : 0.0f;
        #pragma unroll
        for (int o = 16; o > 0; o >>= 1)
            v = fmaxf(v, __shfl_xor_sync(0xFFFFFFFFu, v, o));
        if (lane == 0) g_blockmax[blockIdx.x] = v;
    }

    // ---------------- Grid barrier (flag-flip, replay-safe) ----------------
    __threadfence();                                  // publish g_blockmax
    if (threadIdx.x == 0) {
        unsigned f = g_bar_flag;
        unsigned arrived = atomicAdd(&g_bar_count, 1u);
        if (arrived == BLOCKS - 1) {
            g_bar_count = 0;
            __threadfence();
            g_bar_flag = f ^ 1u;                      // release
        } else {
            while (g_bar_flag == f) { }               // spin (volatile)
        }
    }
    __syncthreads();
    __threadfence();                                  // acquire

    // ---------------- Global max (every block, fixed order) ----------------
    float m = 0.0f;
    for (int i = threadIdx.x; i < BLOCKS; i += NTHREADS)
        m = fmaxf(m, g_blockmax[i]);
    #pragma unroll
    for (int o = 16; o > 0; o >>= 1)
        m = fmaxf(m, __shfl_xor_sync(0xFFFFFFFFu, m, o));
    if (lane == 0) s_red[wid] = m;
    __syncthreads();
    if (wid == 0) {
        float v = (lane < NTHREADS / 32) ? s_red[lane] : 0.0f;
        #pragma unroll
        for (int o = 16; o > 0; o >>= 1)
            v = fmaxf(v, __shfl_xor_sync(0xFFFFFFFFu, v, o));
        if (lane == 0) s_red[0] = v;
    }
    __syncthreads();
    float inv_denom = 1.0f / __fadd_rn(s_red[0], 1e-8f);
    __syncthreads();                                  // s_red reused below

    // ---------------- Phase 2: focal loss from smem ----------------
    float sum = 0.0f;
    for (int i = threadIdx.x; i < cnt; i += NTHREADS) {
        float d    = s_dist[i];
        float g    = 2.0f * __expf(-d);               // dynamic gamma (MUFU)
        float base = 1.0f - sqrtf(d * inv_denom);
        float w    = __expf(g * __logf(base));        // fast pow
        float fl   = w * d;
        sum += fl * fl;
    }

    #pragma unroll
    for (int o = 16; o > 0; o >>= 1)
        sum += __shfl_xor_sync(0xFFFFFFFFu, sum, o);
    if (lane == 0) s_red[wid] = sum;
    __syncthreads();
    if (wid == 0) {
        float v = (lane < NTHREADS / 32) ? s_red[lane] : 0.0f;
        #pragma unroll
        for (int o = 16; o > 0; o >>= 1)
            v += __shfl_xor_sync(0xFFFFFFFFu, v, o);
        if (lane == 0) g_partials[blockIdx.x] = v;
    }

    // ---------------- Last block finishes (deterministic) ----------------
    __shared__ unsigned s_ticket;
    __threadfence();
    if (threadIdx.x == 0)
        s_ticket = atomicAdd(&g_ticket, 1u);
    __syncthreads();
    if (s_ticket == BLOCKS - 1) {
        __threadfence();
        float fs = 0.0f;
        for (int i = threadIdx.x; i < BLOCKS; i += NTHREADS)
            fs += g_partials[i];                      // fixed index order
        #pragma unroll
        for (int o = 16; o > 0; o >>= 1)
            fs += __shfl_xor_sync(0xFFFFFFFFu, fs, o);
        __syncthreads();                              // s_red reuse
        if (lane == 0) s_red[wid] = fs;
        __syncthreads();
        if (wid == 0) {
            float v = (lane < NTHREADS / 32) ? s_red[lane] : 0.0f;
            #pragma unroll
            for (int o = 16; o > 0; o >>= 1)
                v += __shfl_xor_sync(0xFFFFFFFFu, v, o);
            if (lane == 0) {
                out[0] = sqrtf(v / (float)B);
                g_ticket = 0;                         // reset for next replay
            }
        }
    }
}

// ---------------------------------------------------------------------------
extern "C" void kernel_launch(void* const* d_in, const int* in_sizes, int n_in,
                              void* d_out, int out_size) {
    const float* inp = (const float*)d_in[0];   // (B,3) pred ECEF
    const float* tgt = (const float*)d_in[1];   // (B,3) lat/lon/h
    int B = in_sizes[0] / 3;
    float* out = (float*)d_out;

    k_fused<<<BLOCKS, NTHREADS>>>(inp, tgt, out, B);
}

// round 9
// speedup vs baseline: 1.1398x; 1.1398x over previous
#include <cuda_runtime.h>
#include <math.h>

#define B_MAX    4000000
#define BLOCKS   740        // 148 SMs * 5, all co-resident (required for barrier)
#define NTHREADS 256
#define PTS_MAX  5408       // >= ceil(B_MAX / BLOCKS) = 5406

__device__ float             g_blockmax[BLOCKS];
__device__ float             g_partials[BLOCKS];
__device__ unsigned int      g_bar_count = 0;
__device__ volatile unsigned g_bar_flag  = 0;
__device__ unsigned int      g_ticket    = 0;

// ---------------------------------------------------------------------------
__device__ __forceinline__ float rsqrt_ap(float x) {
    float y; asm("rsqrt.approx.f32 %0, %1;" : "=f"(y) : "f"(x)); return y;
}
__device__ __forceinline__ float rcp_ap(float x) {
    float y; asm("rcp.approx.f32 %0, %1;" : "=f"(y) : "f"(x)); return y;
}
__device__ __forceinline__ float sqrt_ap(float x) {
    float y; asm("sqrt.approx.f32 %0, %1;" : "=f"(y) : "f"(x)); return y;
}

// ---------------------------------------------------------------------------
// Double-float sincos for |x| <= pi+eps. f32 sin/cos with abs error ~2^-31,
// matching correctly-rounded f32 (CPU libm) except on a tiny near-tie sliver.
__device__ __forceinline__ void df_sincos(float x, float& s_out, float& c_out) {
    const float TWO_OVER_PI = 0.63661977236758134f;
    const float C1 = 1.57079637050628662109375f;   // float(pi/2)
    const float C2 = -4.37113900018624283e-8f;     // pi/2 - C1 (rounded)

    float qf = rintf(x * TWO_OVER_PI);             // q in {-2..2}
    int   n  = (int)qf;

    float a = fmaf(qf, -C1, x);                    // exact
    float b = -qf * C2;
    float rhi = a + b;                             // TwoSum
    float bp  = rhi - a;
    float rlo = (a - (rhi - bp)) + (b - bp);

    float r2h = rhi * rhi;
    float r2l = fmaf(rhi, rhi, -r2h);
    r2l = fmaf(rhi + rhi, rlo, r2l);

    // ---- sin(r) = r + r^3 * V(r^2), V through r^11 ----
    const float c11 = -2.50521083854417202e-8f;
    const float c9  =  2.75573192239858907e-6f;
    const float c7  = -1.98412698412698413e-4f;
    const float c5  =  8.33333333333333333e-3f;
    const float c3h = -0.16666667163372039794921875f;
    const float c3l =  4.96705424632835143e-9f;

    float Q = fmaf(r2h, c11, c9);
    float T = fmaf(r2h, Q, c7);
    float U = fmaf(r2h, T, c5);
    float ph = r2h * U;
    float pl = fmaf(r2h, U, -ph);
    float vh = c3h + ph;
    float vl = ((c3h - vh) + ph) + pl + c3l;
    float wh = r2h * rhi;                          // r^3
    float wl = fmaf(r2h, rhi, -wh);
    wl = fmaf(r2h, rlo, wl);
    float th = wh * vh;
    float tl = fmaf(wh, vh, -th);
    tl = fmaf(wh, vl, tl);
    tl = fmaf(wl, vh, tl);
    float sh = rhi + th;
    float sl = ((rhi - sh) + th) + tl + rlo;
    float sinr = sh + sl;

    // ---- cos(r) = (1 - r^2/2) + r^4 * E(r^2) ----
    const float e16 =  2.08767569878680990e-9f;
    const float e10 = -2.75573192239858907e-7f;
    const float e8  =  2.48015873015873016e-5f;
    const float e6  = -1.38888888888888889e-3f;
    const float c4h =  0.041666667908430099487304688f;
    const float c4l = -1.24176630587859679e-9f;

    float F = fmaf(r2h, e16, e10);
    F = fmaf(r2h, F, e8);
    F = fmaf(r2h, F, e6);
    float eh0 = r2h * F;
    float el0 = fmaf(r2h, F, -eh0);
    float Eh = c4h + eh0;
    float El = ((c4h - Eh) + eh0) + el0 + c4l;
    float r4h = r2h * r2h;
    float kh = r4h * Eh;
    float kl = fmaf(r4h, Eh, -kh);
    kl = fmaf(r4h, El, kl);
    float hh = 0.5f * r2h;
    float Ah = 1.0f - hh;
    float Al = (1.0f - Ah) - hh;
    Al = fmaf(-0.5f, r2l, Al);
    float ch = Ah + kh;
    float cl = ((Ah - ch) + kh) + kl + Al;
    float cosr = ch + cl;

    int m = n & 3;
    float s = (m & 1) ? cosr : sinr;
    float c = (m & 1) ? sinr : cosr;
    if (m & 2)       s = -s;
    if ((m + 1) & 2) c = -c;
    s_out = s;
    c_out = c;
}

// ---------------------------------------------------------------------------
__device__ __forceinline__ float enu_dist(const float* __restrict__ inp,
                                          const float* __restrict__ tgt, int i) {
    const float DEG2RAD = 0.017453292519943295f;
    const float E2      = 0.00669437999014f;
    const float A       = 6378137.0f;
    const float C1mE2   = 0.99330562000986f;

    float lat = tgt[3 * i + 0];
    float lon = tgt[3 * i + 1];
    float h   = tgt[3 * i + 2];

    float latr = __fmul_rn(lat, DEG2RAD);
    float lonr = __fmul_rn(lon, DEG2RAD);

    float sl, cl, so, co;
    df_sincos(latr, sl, cl);
    df_sincos(lonr, so, co);

    // t = 1 - ((E2*sl)*sl)  (exact reference association)
    float t = __fsub_rn(1.0f, __fmul_rn(__fmul_rn(E2, sl), sl));

    // s = rn(sqrt(t)) via rsqrt + exact-residual Newton (mismatch p ~ 2^-18)
    float y0 = rsqrt_ap(t);
    float s0 = __fmul_rn(t, y0);
    float es = __fmaf_rn(s0, s0, -t);              // s0^2 - t
    float hlf = __fmul_rn(0.5f, y0);               // exact (pow2 scale)
    float s  = __fmaf_rn(es, -hlf, s0);            // rn(s0 - es*h) = rn(sqrt t)

    // N = rn(A / s) via rcp + exact-residual Newton (mismatch p ~ 2^-18)
    float r0 = rcp_ap(s);
    float q0 = __fmul_rn(A, r0);
    float eq = __fmaf_rn(q0, s, -A);               // q0*s - A
    float N  = __fmaf_rn(eq, -r0, q0);             // rn(q0 - eq*r0) = rn(A/s)

    float Nh = __fadd_rn(N, h);
    float Nhcl = __fmul_rn(Nh, cl);
    float rx = __fmul_rn(Nhcl, co);
    float ry = __fmul_rn(Nhcl, so);
    float rz = __fmul_rn(__fadd_rn(__fmul_rn(N, C1mE2), h), sl);

    // small-magnitude path: relative accuracy only
    float dx = __fsub_rn(inp[3 * i + 0], rx);
    float dy = __fsub_rn(inp[3 * i + 1], ry);
    float dz = __fsub_rn(inp[3 * i + 2], rz);

    float e = -so * dx + co * dy;
    float n = -sl * co * dx - sl * so * dy + cl * dz;
    float u =  cl * co * dx + cl * so * dy + sl * dz;

    return sqrt_ap(e * e + n * n + u * u);          // relative-tolerant
}

// ---------------------------------------------------------------------------
// Fused persistent kernel: dist -> smem, grid barrier for global max, focal
// sum, deterministic last-block finish.
__global__ void __launch_bounds__(NTHREADS, 5)
k_fused(const float* __restrict__ inp, const float* __restrict__ tgt,
        float* __restrict__ out, int B) {
    __shared__ float s_dist[PTS_MAX];
    __shared__ float s_red[NTHREADS / 32];

    int chunk = (B + BLOCKS - 1) / BLOCKS;          // <= PTS_MAX
    int start = blockIdx.x * chunk;
    int cnt   = min(chunk, B - start);
    if (cnt < 0) cnt = 0;

    int lane = threadIdx.x & 31, wid = threadIdx.x >> 5;

    // ---------------- Phase 1: distances -> smem, block max ----------------
    float local_max = 0.0f;
    int k = threadIdx.x;
    for (; k + NTHREADS < cnt; k += 2 * NTHREADS) {   // 2-way unroll for ILP
        float d0 = enu_dist(inp, tgt, start + k);
        float d1 = enu_dist(inp, tgt, start + k + NTHREADS);
        s_dist[k] = d0;
        s_dist[k + NTHREADS] = d1;
        local_max = fmaxf(local_max, fmaxf(d0, d1));
    }
    if (k < cnt) {
        float d0 = enu_dist(inp, tgt, start + k);
        s_dist[k] = d0;
        local_max = fmaxf(local_max, d0);
    }

    #pragma unroll
    for (int o = 16; o > 0; o >>= 1)
        local_max = fmaxf(local_max, __shfl_xor_sync(0xFFFFFFFFu, local_max, o));
    if (lane == 0) s_red[wid] = local_max;
    __syncthreads();
    if (wid == 0) {
        float v = (lane < NTHREADS / 32) ? s_red[lane] : 0.0f;
        #pragma unroll
        for (int o = 16; o > 0; o >>= 1)
            v = fmaxf(v, __shfl_xor_sync(0xFFFFFFFFu, v, o));
        if (lane == 0) g_blockmax[blockIdx.x] = v;
    }

    // ---------------- Grid barrier (flag-flip, replay-safe) ----------------
    __threadfence();                                  // publish g_blockmax
    if (threadIdx.x == 0) {
        unsigned f = g_bar_flag;
        unsigned arrived = atomicAdd(&g_bar_count, 1u);
        if (arrived == BLOCKS - 1) {
            g_bar_count = 0;
            __threadfence();
            g_bar_flag = f ^ 1u;                      // release
        } else {
            while (g_bar_flag == f) { }               // spin (volatile)
        }
    }
    __syncthreads();
    __threadfence();                                  // acquire

    // ---------------- Global max (every block, fixed order) ----------------
    float m = 0.0f;
    for (int i = threadIdx.x; i < BLOCKS; i += NTHREADS)
        m = fmaxf(m, g_blockmax[i]);
    #pragma unroll
    for (int o = 16; o > 0; o >>= 1)
        m = fmaxf(m, __shfl_xor_sync(0xFFFFFFFFu, m, o));
    if (lane == 0) s_red[wid] = m;
    __syncthreads();
    if (wid == 0) {
        float v = (lane < NTHREADS / 32) ? s_red[lane] : 0.0f;
        #pragma unroll
        for (int o = 16; o > 0; o >>= 1)
            v = fmaxf(v, __shfl_xor_sync(0xFFFFFFFFu, v, o));
        if (lane == 0) s_red[0] = v;
    }
    __syncthreads();
    float inv_denom = 1.0f / __fadd_rn(s_red[0], 1e-8f);
    __syncthreads();                                  // s_red reused below

    // ---------------- Phase 2: focal loss from smem ----------------
    float sum = 0.0f;
    for (int i = threadIdx.x; i < cnt; i += NTHREADS) {
        float d    = s_dist[i];
        float g    = 2.0f * __expf(-d);               // dynamic gamma (MUFU)
        float base = 1.0f - sqrt_ap(d * inv_denom);
        float w    = __expf(g * __logf(base));        // fast pow
        float fl   = w * d;
        sum += fl * fl;
    }

    #pragma unroll
    for (int o = 16; o > 0; o >>= 1)
        sum += __shfl_xor_sync(0xFFFFFFFFu, sum, o);
    if (lane == 0) s_red[wid] = sum;
    __syncthreads();
    if (wid == 0) {
        float v = (lane < NTHREADS / 32) ? s_red[lane] : 0.0f;
        #pragma unroll
        for (int o = 16; o > 0; o >>= 1)
            v += __shfl_xor_sync(0xFFFFFFFFu, v, o);
        if (lane == 0) g_partials[blockIdx.x] = v;
    }

    // ---------------- Last block finishes (deterministic) ----------------
    __shared__ unsigned s_ticket;
    __threadfence();
    if (threadIdx.x == 0)
        s_ticket = atomicAdd(&g_ticket, 1u);
    __syncthreads();
    if (s_ticket == BLOCKS - 1) {
        __threadfence();
        float fs = 0.0f;
        for (int i = threadIdx.x; i < BLOCKS; i += NTHREADS)
            fs += g_partials[i];                      // fixed index order
        #pragma unroll
        for (int o = 16; o > 0; o >>= 1)
            fs += __shfl_xor_sync(0xFFFFFFFFu, fs, o);
        __syncthreads();                              // s_red reuse
        if (lane == 0) s_red[wid] = fs;
        __syncthreads();
        if (wid == 0) {
            float v = (lane < NTHREADS / 32) ? s_red[lane] : 0.0f;
            #pragma unroll
            for (int o = 16; o > 0; o >>= 1)
                v += __shfl_xor_sync(0xFFFFFFFFu, v, o);
            if (lane == 0) {
                out[0] = sqrtf(v / (float)B);
                g_ticket = 0;                         // reset for next replay
            }
        }
    }
}

// ---------------------------------------------------------------------------
extern "C" void kernel_launch(void* const* d_in, const int* in_sizes, int n_in,
                              void* d_out, int out_size) {
    const float* inp = (const float*)d_in[0];   // (B,3) pred ECEF
    const float* tgt = (const float*)d_in[1];   // (B,3) lat/lon/h
    int B = in_sizes[0] / 3;
    float* out = (float*)d_out;

    k_fused<<<BLOCKS, NTHREADS>>>(inp, tgt, out, B);
}